// round 12
// baseline (speedup 1.0000x reference)
#include <cuda_runtime.h>
#include <cstdint>
#include <math.h>

// ---------------------------------------------------------------------------
// Threefry-2x32 (exact JAX implementation: jax/_src/prng.py)
// ---------------------------------------------------------------------------
__host__ __device__ __forceinline__ void threefry2x32(
    unsigned k0, unsigned k1, unsigned x0, unsigned x1,
    unsigned &o0, unsigned &o1)
{
    const unsigned ks2 = k0 ^ k1 ^ 0x1BD11BDAu;
    unsigned a = x0 + k0, b = x1 + k1;
#define TF_ROT(v,d) (((v)<<(d))|((v)>>(32-(d))))
#define TF_R4(r0_,r1_,r2_,r3_) \
    a+=b; b=TF_ROT(b,r0_); b^=a; \
    a+=b; b=TF_ROT(b,r1_); b^=a; \
    a+=b; b=TF_ROT(b,r2_); b^=a; \
    a+=b; b=TF_ROT(b,r3_); b^=a;
    TF_R4(13,15,26, 6);  a+=k1;  b+=ks2+1u;
    TF_R4(17,29,16,24);  a+=ks2; b+=k0 +2u;
    TF_R4(13,15,26, 6);  a+=k0;  b+=k1 +3u;
    TF_R4(17,29,16,24);  a+=k1;  b+=ks2+4u;
    TF_R4(13,15,26, 6);  a+=ks2; b+=k0 +5u;
    o0 = a; o1 = b;
#undef TF_R4
#undef TF_ROT
}

// ---------------------------------------------------------------------------
// Packed fp32x2 helpers (sm_103a FFMA2 — 2x FFMA throughput)
// ---------------------------------------------------------------------------
__device__ __forceinline__ unsigned long long pack_dup(float a) {
    unsigned long long r;
    asm("mov.b64 %0, {%1, %1};" : "=l"(r) : "f"(a));
    return r;
}
__device__ __forceinline__ unsigned long long fma2(
    unsigned long long a, unsigned long long b, unsigned long long c) {
    unsigned long long d;
    asm("fma.rn.f32x2 %0, %1, %2, %3;" : "=l"(d) : "l"(a), "l"(b), "l"(c));
    return d;
}

// ---------------------------------------------------------------------------
// GEMM: out[T,128] = H[T,D] @ W[D,128], fp32 accurate.
// Tile 64x128xBK16, 256 threads, 4x8 micro-tiles, occupancy 2 (16 warps/SM).
// A stored in smem as duplicated fp32 pairs -> no dup-MOVs in inner loop.
// Inner k-step: 4 LDS.128 + 16 FFMA2.
// ---------------------------------------------------------------------------
#define AS_LD 132   // padded row stride (floats) for dup-A plane, 16B aligned

__global__ __launch_bounds__(256, 2)
void gemm64(const float* __restrict__ H, const float* __restrict__ W,
            float* __restrict__ out, int D)
{
    __shared__ float As2[16][AS_LD];   // dup pairs: As2[k][2m]=As2[k][2m+1]=a[m]
    __shared__ float Bs [16][128];

    const int tid = threadIdx.x;
    const int bm  = blockIdx.x * 64;

    // compute-thread mapping: 16x16 grid
    const int trow = tid >> 4;          // 0..15
    const int tcol = tid & 15;          // 0..15
    const int m0   = trow * 4;          // 0..60
    const int n0   = tcol * 4;

    // load mapping
    const int lrow = tid >> 2;          // 0..63 (A rows)
    const int lkq  = (tid & 3) * 4;     // k offset within BK
    const int bkr  = tid >> 5;          // 0..7  (B k rows; +8 second half)
    const int bc   = (tid & 31) * 4;    // B column

    const float* hPtr = H + (size_t)(bm + lrow) * (size_t)D + lkq;
    const float* wPtr = W + bkr * 128 + bc;

    // acc[mi][pj]: row m0+mi; pj -> n pair at {n0, n0+2, n0+64, n0+66}
    unsigned long long acc[4][4];
#pragma unroll
    for (int i = 0; i < 4; i++)
#pragma unroll
        for (int j = 0; j < 4; j++) acc[i][j] = 0ull;

    const int nIter = D / 16;

    // preload tile 0
    float4 ra  = *(const float4*)(hPtr);
    float4 rb0 = *(const float4*)(wPtr);
    float4 rb1 = *(const float4*)(wPtr + 8 * 128);

    for (int it = 0; it < nIter; ++it) {
        // store current tile to smem: A transposed + duplicated pairs
        *(unsigned long long*)&As2[lkq + 0][2 * lrow] = pack_dup(ra.x);
        *(unsigned long long*)&As2[lkq + 1][2 * lrow] = pack_dup(ra.y);
        *(unsigned long long*)&As2[lkq + 2][2 * lrow] = pack_dup(ra.z);
        *(unsigned long long*)&As2[lkq + 3][2 * lrow] = pack_dup(ra.w);
        *(float4*)&Bs[bkr    ][bc] = rb0;
        *(float4*)&Bs[bkr + 8][bc] = rb1;
        __syncthreads();

        // prefetch next tile into registers (hidden under compute)
        if (it + 1 < nIter) {
            ra  = *(const float4*)(hPtr + (size_t)(it + 1) * 16);
            const float* wp = wPtr + (size_t)(it + 1) * 16 * 128;
            rb0 = *(const float4*)(wp);
            rb1 = *(const float4*)(wp + 8 * 128);
        }

#pragma unroll
        for (int k = 0; k < 16; ++k) {
            // A: 2x LDS.128 broadcast (dup pairs m0..m0+3)
            ulonglong2 la0 = *(const ulonglong2*)&As2[k][2 * m0];
            ulonglong2 la1 = *(const ulonglong2*)&As2[k][2 * m0 + 4];
            // B: 2x LDS.128 (pairs n0,n0+2 and n0+64,n0+66)
            ulonglong2 lb0 = *(const ulonglong2*)&Bs[k][n0];
            ulonglong2 lb1 = *(const ulonglong2*)&Bs[k][n0 + 64];
            unsigned long long ap[4] = { la0.x, la0.y, la1.x, la1.y };
#pragma unroll
            for (int mi = 0; mi < 4; ++mi) {
                acc[mi][0] = fma2(ap[mi], lb0.x, acc[mi][0]);
                acc[mi][1] = fma2(ap[mi], lb0.y, acc[mi][1]);
                acc[mi][2] = fma2(ap[mi], lb1.x, acc[mi][2]);
                acc[mi][3] = fma2(ap[mi], lb1.y, acc[mi][3]);
            }
        }
        __syncthreads();
    }

    // writeback: two 16B stores per row
#pragma unroll
    for (int mi = 0; mi < 4; ++mi) {
        const size_t m = (size_t)(bm + m0 + mi);
        ulonglong2 v0; v0.x = acc[mi][0]; v0.y = acc[mi][1];
        ulonglong2 v1; v1.x = acc[mi][2]; v1.y = acc[mi][3];
        *(ulonglong2*)&out[m * 128 + n0]      = v0;
        *(ulonglong2*)&out[m * 128 + n0 + 64] = v1;
    }
}

// ---------------------------------------------------------------------------
// Epilogue: one WARP per token (R5/R11, measured 26us).
// ---------------------------------------------------------------------------
__global__ __launch_bounds__(128)
void router_epilogue(const float* __restrict__ logits,
                     const int* __restrict__ tmask,   // 4-byte bool
                     float* __restrict__ out_mask,
                     float* __restrict__ out_probs,
                     float* __restrict__ out_lsel,
                     unsigned fk0, unsigned fk1)
{
    const int lane = threadIdx.x & 31;
    const int t    = blockIdx.x * 4 + (threadIdx.x >> 5);
    const unsigned base = (unsigned)t * 128u + (unsigned)lane * 4u;

    const float4 l4 = *(const float4*)&logits[base];
    float lc[4] = { l4.x, l4.y, l4.z, l4.w };
    const bool tm = (tmask[t] != 0);

    // --- JAX-exact gumbel (jax_threefry_partitionable=True): bits = o0^o1 ---
    float lsm[4];
#pragma unroll
    for (int j = 0; j < 4; ++j) {
        unsigned o0, o1;
        threefry2x32(fk0, fk1, 0u, base + (unsigned)j, o0, o1);
        const unsigned bits = o0 ^ o1;
        float f = __uint_as_float((bits >> 9) | 0x3f800000u) - 1.0f;
        const float minv = 1e-6f;
        const float maxv = (float)(1.0 - 1e-6);
        float u = fmaxf(minv, f * (maxv - minv) + minv);
        const float g = -logf(-logf(u));
        lsm[j] = tm ? (lc[j] + g) : -INFINITY;
    }

    // --- top-8: iterative warp argmax (ties -> lowest global index) --------
    float v[4] = { lsm[0], lsm[1], lsm[2], lsm[3] };
    bool sel[4] = { false, false, false, false };
#pragma unroll 1
    for (int it = 0; it < 8; ++it) {
        float bv = v[0];
        int   bg = lane * 4;
#pragma unroll
        for (int j = 1; j < 4; ++j)
            if (v[j] > bv) { bv = v[j]; bg = lane * 4 + j; }
#pragma unroll
        for (int off = 16; off; off >>= 1) {
            float ov = __shfl_xor_sync(0xffffffffu, bv, off);
            int   og = __shfl_xor_sync(0xffffffffu, bg, off);
            if (ov > bv || (ov == bv && og < bg)) { bv = ov; bg = og; }
        }
#pragma unroll
        for (int j = 0; j < 4; ++j)
            if (bg == lane * 4 + j) { sel[j] = true; v[j] = -INFINITY; }
    }

    // --- softmax over clean logits ----------------------------------------
    float mx = fmaxf(fmaxf(lc[0], lc[1]), fmaxf(lc[2], lc[3]));
#pragma unroll
    for (int off = 16; off; off >>= 1)
        mx = fmaxf(mx, __shfl_xor_sync(0xffffffffu, mx, off));

    float ex[4];
    float s = 0.0f;
#pragma unroll
    for (int j = 0; j < 4; ++j) { ex[j] = expf(lc[j] - mx); s += ex[j]; }
#pragma unroll
    for (int off = 16; off; off >>= 1)
        s += __shfl_xor_sync(0xffffffffu, s, off);

    float p[4];
#pragma unroll
    for (int j = 0; j < 4; ++j) p[j] = tm ? (ex[j] / s) : 0.0f;

    // --- masked renorm -----------------------------------------------------
    float ms = 0.0f;
#pragma unroll
    for (int j = 0; j < 4; ++j) if (sel[j]) ms += p[j];
#pragma unroll
    for (int off = 16; off; off >>= 1)
        ms += __shfl_xor_sync(0xffffffffu, ms, off);
    const float den = fmaxf(ms, 1e-9f);

    float4 omask, oprob, osel;
    float* om = &omask.x; float* op = &oprob.x; float* os = &osel.x;
#pragma unroll
    for (int j = 0; j < 4; ++j) {
        float pr = sel[j] ? (p[j] / den) : 0.0f;
        om[j] = (sel[j] && tm) ? 1.0f : 0.0f;
        op[j] = tm ? pr : 0.0f;
        os[j] = lsm[j];
    }
    *(float4*)&out_mask [base] = omask;
    *(float4*)&out_probs[base] = oprob;
    *(float4*)&out_lsel [base] = osel;
}

// ---------------------------------------------------------------------------
// launch
// ---------------------------------------------------------------------------
extern "C" void kernel_launch(void* const* d_in, const int* in_sizes, int n_in,
                              void* d_out, int out_size)
{
    const float* H  = (const float*)d_in[0];
    const float* W  = (const float*)d_in[1];
    const int*   tm = (const int*)d_in[2];     // bool promoted to 4-byte

    const int T = in_sizes[2];                 // 16384
    const int D = in_sizes[0] / T;             // 4096

    float* outF      = (float*)d_out;
    const unsigned TE = (unsigned)T * 128u;
    float* out_mask  = outF;
    float* out_probs = outF + TE;
    float* out_clean = outF + 2u * TE;
    float* out_sel   = outF + 3u * TE;

    gemm64<<<T / 64, 256>>>(H, W, out_clean, D);

    // folded key: fold_in(key(7), 1) = threefry([0,7], [0,1])
    unsigned fk0, fk1;
    threefry2x32(0u, 7u, 0u, 1u, fk0, fk1);

    router_epilogue<<<T / 4, 128>>>(out_clean, tm, out_mask, out_probs, out_sel,
                                    fk0, fk1);
}

// round 13
// speedup vs baseline: 1.4343x; 1.4343x over previous
#include <cuda_runtime.h>
#include <cstdint>
#include <math.h>

// ---------------------------------------------------------------------------
// Threefry-2x32 (exact JAX implementation: jax/_src/prng.py)
// ---------------------------------------------------------------------------
__host__ __device__ __forceinline__ void threefry2x32(
    unsigned k0, unsigned k1, unsigned x0, unsigned x1,
    unsigned &o0, unsigned &o1)
{
    const unsigned ks2 = k0 ^ k1 ^ 0x1BD11BDAu;
    unsigned a = x0 + k0, b = x1 + k1;
#define TF_ROT(v,d) (((v)<<(d))|((v)>>(32-(d))))
#define TF_R4(r0_,r1_,r2_,r3_) \
    a+=b; b=TF_ROT(b,r0_); b^=a; \
    a+=b; b=TF_ROT(b,r1_); b^=a; \
    a+=b; b=TF_ROT(b,r2_); b^=a; \
    a+=b; b=TF_ROT(b,r3_); b^=a;
    TF_R4(13,15,26, 6);  a+=k1;  b+=ks2+1u;
    TF_R4(17,29,16,24);  a+=ks2; b+=k0 +2u;
    TF_R4(13,15,26, 6);  a+=k0;  b+=k1 +3u;
    TF_R4(17,29,16,24);  a+=k1;  b+=ks2+4u;
    TF_R4(13,15,26, 6);  a+=ks2; b+=k0 +5u;
    o0 = a; o1 = b;
#undef TF_R4
#undef TF_ROT
}

// ---------------------------------------------------------------------------
// Packed fp32x2 helpers (sm_103a FFMA2 — 2x FFMA throughput)
// ---------------------------------------------------------------------------
__device__ __forceinline__ unsigned long long pack_dup(float a) {
    unsigned long long r;
    asm("mov.b64 %0, {%1, %1};" : "=l"(r) : "f"(a));
    return r;
}
__device__ __forceinline__ unsigned long long fma2(
    unsigned long long a, unsigned long long b, unsigned long long c) {
    unsigned long long d;
    asm("fma.rn.f32x2 %0, %1, %2, %3;" : "=l"(d) : "l"(a), "l"(b), "l"(c));
    return d;
}

// ---------------------------------------------------------------------------
// k-split partial planes: 8 x [T,128] fp32 scratch (static device memory)
// ---------------------------------------------------------------------------
#define MAX_T   16384
#define NSPLIT  8
#define KOCT    512                      // k per octave (D=4096 / 8)
__device__ float g_part[(size_t)NSPLIT * MAX_T * 128];

// ---------------------------------------------------------------------------
// Persistent k-split GEMM.  Work unit = (m-tile 128 rows) x (k-octave 512).
// 1024 units over gridDim CTAs.  Inner body identical to R4/R11 (measured).
// ---------------------------------------------------------------------------
__global__ __launch_bounds__(256, 1)
void gemm_ksplit(const float* __restrict__ H, const float* __restrict__ W,
                 int D, int T)
{
    __shared__ float As[16][132];   // transposed h tile (padded rows)
    __shared__ float Bs[16][128];

    const int tid = threadIdx.x;

    // compute-thread mapping: 16x16 grid, 4+4 split in each dim
    const int trow = tid >> 4;          // 0..15
    const int tcol = tid & 15;          // 0..15
    const int m0   = trow * 4;
    const int n0   = tcol * 4;

    // load mapping
    const int lrow = tid >> 2;          // 0..63 (A rows; +64 for second half)
    const int lkq  = (tid & 3) * 4;     // k offset within BK
    const int bkr  = tid >> 5;          // 0..7  (B k rows; +8 second half)
    const int bc   = (tid & 31) * 4;    // B column

    const int nTiles = T / 128;                 // 128
    const int nUnits = nTiles * NSPLIT;         // 1024
    const int nIter  = KOCT / 16;               // 32

    for (int unit = blockIdx.x; unit < nUnits; unit += gridDim.x) {
        const int tile = unit >> 3;
        const int oct  = unit & 7;
        const int bm   = tile * 128;
        const int kb   = oct * KOCT;

        const float* hPtr = H + (size_t)(bm + lrow) * (size_t)D + kb + lkq;
        const float* wPtr = W + (size_t)(kb + bkr) * 128 + bc;

        unsigned long long acc[8][4];
#pragma unroll
        for (int i = 0; i < 8; i++)
#pragma unroll
            for (int j = 0; j < 4; j++) acc[i][j] = 0ull;

        // preload first BK16 slab of this unit
        float4 ra0 = *(const float4*)(hPtr);
        float4 ra1 = *(const float4*)(hPtr + (size_t)64 * D);
        float4 rb0 = *(const float4*)(wPtr);
        float4 rb1 = *(const float4*)(wPtr + 8 * 128);

        for (int it = 0; it < nIter; ++it) {
            As[lkq + 0][lrow]      = ra0.x;
            As[lkq + 1][lrow]      = ra0.y;
            As[lkq + 2][lrow]      = ra0.z;
            As[lkq + 3][lrow]      = ra0.w;
            As[lkq + 0][lrow + 64] = ra1.x;
            As[lkq + 1][lrow + 64] = ra1.y;
            As[lkq + 2][lrow + 64] = ra1.z;
            As[lkq + 3][lrow + 64] = ra1.w;
            *(float4*)&Bs[bkr    ][bc] = rb0;
            *(float4*)&Bs[bkr + 8][bc] = rb1;
            __syncthreads();

            if (it + 1 < nIter) {
                const float* hp = hPtr + (size_t)(it + 1) * 16;
                ra0 = *(const float4*)(hp);
                ra1 = *(const float4*)(hp + (size_t)64 * D);
                const float* wp = wPtr + (size_t)(it + 1) * 16 * 128;
                rb0 = *(const float4*)(wp);
                rb1 = *(const float4*)(wp + 8 * 128);
            }

#pragma unroll
            for (int k = 0; k < 16; ++k) {
                float4 a0 = *(const float4*)&As[k][m0];
                float4 a1 = *(const float4*)&As[k][m0 + 64];
                unsigned long long bp[4];
                bp[0] = *(const unsigned long long*)&Bs[k][n0];
                bp[1] = *(const unsigned long long*)&Bs[k][n0 + 2];
                bp[2] = *(const unsigned long long*)&Bs[k][n0 + 64];
                bp[3] = *(const unsigned long long*)&Bs[k][n0 + 66];
                unsigned long long ap[8];
                ap[0] = pack_dup(a0.x); ap[1] = pack_dup(a0.y);
                ap[2] = pack_dup(a0.z); ap[3] = pack_dup(a0.w);
                ap[4] = pack_dup(a1.x); ap[5] = pack_dup(a1.y);
                ap[6] = pack_dup(a1.z); ap[7] = pack_dup(a1.w);
#pragma unroll
                for (int mi = 0; mi < 8; ++mi)
#pragma unroll
                    for (int pj = 0; pj < 4; ++pj)
                        acc[mi][pj] = fma2(ap[mi], bp[pj], acc[mi][pj]);
            }
            __syncthreads();
        }

        // writeback partial into plane `oct`
        float* plane = g_part + (size_t)oct * T * 128;
#pragma unroll
        for (int mi = 0; mi < 8; ++mi) {
            const int m = bm + m0 + (mi & 3) + ((mi >> 2) << 6);
#pragma unroll
            for (int pj = 0; pj < 4; ++pj) {
                const int n = n0 + ((pj & 1) << 1) + ((pj >> 1) << 6);
                *(unsigned long long*)&plane[(size_t)m * 128 + n] = acc[mi][pj];
            }
        }
        // next unit's STS is safe: last __syncthreads above fenced compute
    }
}

// ---------------------------------------------------------------------------
// Epilogue: one WARP per token.  Sums the 8 k-split partials (fixed order),
// writes logits_clean, then gumbel/top-8/softmax/renorm as before.
// ---------------------------------------------------------------------------
__global__ __launch_bounds__(128)
void router_epilogue(const int* __restrict__ tmask,
                     float* __restrict__ out_mask,
                     float* __restrict__ out_probs,
                     float* __restrict__ out_clean,
                     float* __restrict__ out_lsel,
                     int T, unsigned fk0, unsigned fk1)
{
    const int lane = threadIdx.x & 31;
    const int t    = blockIdx.x * 4 + (threadIdx.x >> 5);
    const unsigned base = (unsigned)t * 128u + (unsigned)lane * 4u;

    // sum 8 partial planes (fixed ascending order -> deterministic)
    float4 a4 = make_float4(0.f, 0.f, 0.f, 0.f);
#pragma unroll
    for (int p = 0; p < NSPLIT; ++p) {
        const float4 v = *(const float4*)&g_part[(size_t)p * T * 128 + base];
        a4.x += v.x; a4.y += v.y; a4.z += v.z; a4.w += v.w;
    }
    float lc[4] = { a4.x, a4.y, a4.z, a4.w };
    *(float4*)&out_clean[base] = a4;

    const bool tm = (tmask[t] != 0);

    // --- JAX-exact gumbel (jax_threefry_partitionable=True): bits = o0^o1 ---
    float lsm[4];
#pragma unroll
    for (int j = 0; j < 4; ++j) {
        unsigned o0, o1;
        threefry2x32(fk0, fk1, 0u, base + (unsigned)j, o0, o1);
        const unsigned bits = o0 ^ o1;
        float f = __uint_as_float((bits >> 9) | 0x3f800000u) - 1.0f;
        const float minv = 1e-6f;
        const float maxv = (float)(1.0 - 1e-6);
        float u = fmaxf(minv, f * (maxv - minv) + minv);
        const float g = -logf(-logf(u));
        lsm[j] = tm ? (lc[j] + g) : -INFINITY;
    }

    // --- top-8: iterative warp argmax (ties -> lowest global index) --------
    float v[4] = { lsm[0], lsm[1], lsm[2], lsm[3] };
    bool sel[4] = { false, false, false, false };
#pragma unroll 1
    for (int it = 0; it < 8; ++it) {
        float bv = v[0];
        int   bg = lane * 4;
#pragma unroll
        for (int j = 1; j < 4; ++j)
            if (v[j] > bv) { bv = v[j]; bg = lane * 4 + j; }
#pragma unroll
        for (int off = 16; off; off >>= 1) {
            float ov = __shfl_xor_sync(0xffffffffu, bv, off);
            int   og = __shfl_xor_sync(0xffffffffu, bg, off);
            if (ov > bv || (ov == bv && og < bg)) { bv = ov; bg = og; }
        }
#pragma unroll
        for (int j = 0; j < 4; ++j)
            if (bg == lane * 4 + j) { sel[j] = true; v[j] = -INFINITY; }
    }

    // --- softmax over clean logits ----------------------------------------
    float mx = fmaxf(fmaxf(lc[0], lc[1]), fmaxf(lc[2], lc[3]));
#pragma unroll
    for (int off = 16; off; off >>= 1)
        mx = fmaxf(mx, __shfl_xor_sync(0xffffffffu, mx, off));

    float ex[4];
    float s = 0.0f;
#pragma unroll
    for (int j = 0; j < 4; ++j) { ex[j] = expf(lc[j] - mx); s += ex[j]; }
#pragma unroll
    for (int off = 16; off; off >>= 1)
        s += __shfl_xor_sync(0xffffffffu, s, off);

    float p[4];
#pragma unroll
    for (int j = 0; j < 4; ++j) p[j] = tm ? (ex[j] / s) : 0.0f;

    // --- masked renorm -----------------------------------------------------
    float ms = 0.0f;
#pragma unroll
    for (int j = 0; j < 4; ++j) if (sel[j]) ms += p[j];
#pragma unroll
    for (int off = 16; off; off >>= 1)
        ms += __shfl_xor_sync(0xffffffffu, ms, off);
    const float den = fmaxf(ms, 1e-9f);

    float4 omask, oprob, osel;
    float* om = &omask.x; float* op = &oprob.x; float* os = &osel.x;
#pragma unroll
    for (int j = 0; j < 4; ++j) {
        float pr = sel[j] ? (p[j] / den) : 0.0f;
        om[j] = (sel[j] && tm) ? 1.0f : 0.0f;
        op[j] = tm ? pr : 0.0f;
        os[j] = lsm[j];
    }
    *(float4*)&out_mask [base] = omask;
    *(float4*)&out_probs[base] = oprob;
    *(float4*)&out_lsel [base] = osel;
}

// ---------------------------------------------------------------------------
// launch
// ---------------------------------------------------------------------------
extern "C" void kernel_launch(void* const* d_in, const int* in_sizes, int n_in,
                              void* d_out, int out_size)
{
    const float* H  = (const float*)d_in[0];
    const float* W  = (const float*)d_in[1];
    const int*   tm = (const int*)d_in[2];     // bool promoted to 4-byte

    const int T = in_sizes[2];                 // 16384
    const int D = in_sizes[0] / T;             // 4096

    float* outF      = (float*)d_out;
    const unsigned TE = (unsigned)T * 128u;
    float* out_mask  = outF;
    float* out_probs = outF + TE;
    float* out_clean = outF + 2u * TE;
    float* out_sel   = outF + 3u * TE;

    gemm_ksplit<<<148, 256>>>(H, W, D, T);

    // folded key: fold_in(key(7), 1) = threefry([0,7], [0,1])
    unsigned fk0, fk1;
    threefry2x32(0u, 7u, 0u, 1u, fk0, fk1);

    router_epilogue<<<T / 4, 128>>>(tm, out_mask, out_probs, out_clean, out_sel,
                                    T, fk0, fk1);
}